// round 10
// baseline (speedup 1.0000x reference)
#include <cuda_runtime.h>
#include <stdint.h>
#include <math.h>

#define NB 128      // batch
#define NT 512      // time steps
#define ND 256      // input dim
#define NH 512      // hidden dim
#define NG 2048     // 4*NH
#define NCTA 128    // persistent grid size (all resident)
#define KC 64       // K-chunk for recurrent GEMM
#define HP 132      // smem pitch (floats) for transposed h chunk; 528B = 33*16B
#define NCHUNK (NH / KC)   // 8
#define NGROUP 8           // CTA groups of 16; group G produces h cols [G*64,(G+1)*64)

// packed fp32x2 FMA: d.lo += a.lo*b.lo, d.hi += a.hi*b.hi  (one fma-pipe instr)
#define FMA2(d, a, b) \
    asm("fma.rn.f32x2 %0, %1, %2, %0;" : "+l"(d) : "l"(a), "l"(b))
#define PACK2(out, v) \
    asm("mov.b64 %0, {%1, %1};" : "=l"(out) : "r"(__float_as_uint(v)))

// -------------------- device scratch (no allocs allowed) --------------------
// zx stored TRANSPOSED: g_zx[t][col][b]  (col = gate*512 + hj)
__device__ float g_zx[(size_t)NT * NG * NB];
__device__ float g_hbuf[2][NH * NB];           // transposed hidden state: [hj][b]
__device__ unsigned g_arrive[NGROUP];          // monotonic per-group arrival counters
__device__ unsigned g_gemm_done;               // monotonic completed-GEMM counter

// -------------------- cp.async helpers --------------------
__device__ __forceinline__ void cpa16(uint32_t dst_smem, const void* src) {
    asm volatile("cp.async.cg.shared.global [%0], [%1], 16;\n"
                 :: "r"(dst_smem), "l"(src));
}
__device__ __forceinline__ void cpa_commit() {
    asm volatile("cp.async.commit_group;\n");
}
__device__ __forceinline__ void cpa_wait0() {
    asm volatile("cp.async.wait_group 0;\n");
}

// -------------------- flag wait (acquire) --------------------
__device__ __forceinline__ void wait_ge(const unsigned* p, unsigned target) {
    unsigned v;
    asm volatile("ld.acquire.gpu.global.u32 %0, [%1];" : "=r"(v) : "l"(p));
    while (v < target) {
        __nanosleep(64);
        asm volatile("ld.acquire.gpu.global.u32 %0, [%1];" : "=r"(v) : "l"(p));
    }
}
__device__ __forceinline__ void red_add(unsigned* p, unsigned v) {
    asm volatile("red.relaxed.gpu.global.add.u32 [%0], %1;" :: "l"(p), "r"(v));
}

// -------------------- fast activations (budget: rel_err < 1e-3) ------------
__device__ __forceinline__ float fsigmoid(float x) {
    return 1.f / (1.f + __expf(-x));
}
__device__ __forceinline__ float ftanh(float x) {
    return 1.f - 2.f / (1.f + __expf(2.f * x));
}

// -------------------- init kernel: reset counters each replay ---------------
__global__ void sync_init() {
    if (threadIdx.x < NGROUP) g_arrive[threadIdx.x] = 0u;
    if (threadIdx.x == NGROUP) g_gemm_done = 0u;
}

// -------------------- Phase 1: zx_t[t][col][b] = (x@Wx + b) transposed ------
// M = T*B, N = 2048, K = 256. Tile 128x64, 256 thr, 8x4 micro (f32x2 packed).
__global__ void __launch_bounds__(256) zx_gemm(const float* __restrict__ x,
                                               const float* __restrict__ Wx,
                                               const float* __restrict__ bias) {
    __shared__ float shAT[16 * HP];   // [kk][b] transposed A tile
    __shared__ float shB[16 * 64];    // [kk][j]

    const int nt = blockIdx.x;        // 0..31
    const int mt = blockIdx.y;        // 0..511  (== t, tile M = 128 = NB)
    const int tid = threadIdx.x;
    const int c0 = (tid & 15) << 2;
    const int r0 = (tid >> 4) << 3;

    unsigned long long acc2[4][4];    // [row-pair][col], packed fp32x2
#pragma unroll
    for (int p = 0; p < 4; ++p)
#pragma unroll
        for (int c = 0; c < 4; ++c) acc2[p][c] = 0ull;

    for (int k0 = 0; k0 < ND; k0 += 16) {
#pragma unroll
        for (int i = 0; i < 8; ++i) {
            int flat = i * 256 + tid;
            int kk = flat & 15;
            int b = flat >> 4;
            shAT[kk * HP + b] = x[(size_t)b * (NT * ND) + (size_t)mt * ND + k0 + kk];
        }
#pragma unroll
        for (int i = 0; i < 4; ++i) {
            int flat = i * 256 + tid;
            int j = flat & 63;
            int kk = flat >> 6;
            shB[kk * 64 + j] = Wx[(size_t)(k0 + kk) * NG + nt * 64 + j];
        }
        __syncthreads();
#pragma unroll
        for (int kk = 0; kk < 16; ++kk) {
            const float4 b4 = *(const float4*)&shB[kk * 64 + c0];
            unsigned long long bd[4];
            PACK2(bd[0], b4.x); PACK2(bd[1], b4.y);
            PACK2(bd[2], b4.z); PACK2(bd[3], b4.w);
            const ulonglong2 a01 = *(const ulonglong2*)&shAT[kk * HP + r0];
            const ulonglong2 a23 = *(const ulonglong2*)&shAT[kk * HP + r0 + 4];
            const unsigned long long ap[4] = {a01.x, a01.y, a23.x, a23.y};
#pragma unroll
            for (int p = 0; p < 4; ++p)
#pragma unroll
                for (int c = 0; c < 4; ++c) FMA2(acc2[p][c], ap[p], bd[c]);
        }
        __syncthreads();
    }

    // unpack + bias, store transposed: g_zx[(mt*NG + col)*NB + b]
#pragma unroll
    for (int c = 0; c < 4; ++c) {
        const float bc = bias[nt * 64 + c0 + c];
        float a[8];
#pragma unroll
        for (int p = 0; p < 4; ++p) {
            a[2 * p]     = __uint_as_float((unsigned)(acc2[p][c] & 0xFFFFFFFFull)) + bc;
            a[2 * p + 1] = __uint_as_float((unsigned)(acc2[p][c] >> 32)) + bc;
        }
        size_t base = ((size_t)mt * NG + nt * 64 + c0 + c) * NB + r0;
        *(float4*)&g_zx[base]     = make_float4(a[0], a[1], a[2], a[3]);
        *(float4*)&g_zx[base + 4] = make_float4(a[4], a[5], a[6], a[7]);
    }
}

// -------------------- Phase 2: persistent recurrent kernel ------------------
// CTA g owns h-columns [4g, 4g+4) and z-columns {gate*512 + 4g + w}.
// Flag-based producer/consumer sync (no global barrier); cp.async double-
// buffered h chunks; inner GEMM in packed f32x2 (weights pre-duplicated).
__global__ void __launch_bounds__(256, 1) lstm_persistent(
    const float* __restrict__ Wh, float* __restrict__ out) {
    extern __shared__ float smem[];
    float* sh_wh2 = smem;                              // [512][16] float2 = 16384 floats
    float* sh_h   = smem + NH * 16 * 2;                // [2][KC][HP]
    float* sh_z   = smem + NH * 16 * 2 + 2 * KC * HP;  // [128][16]

    const int g = blockIdx.x;    // 0..127
    const int tid = threadIdx.x;
    const int grp = g >> 4;      // own producer group

    // Wh slice, duplicated into both lanes of a float2 (one 8B LDS per kk)
    for (int i = tid; i < NH * 16; i += 256) {
        int k = i >> 4, c = i & 15;
        int gcol = ((c >> 2) << 9) + (g << 2) + (c & 3);  // gate*512 + 4g + w
        float wv = Wh[(size_t)k * NG + gcol];
        ((float2*)sh_wh2)[i] = make_float2(wv, wv);
    }

    const int col = tid & 15;
    const int rb = (tid >> 4) << 3;
    const int gcol = ((col >> 2) << 9) + (g << 2) + (col & 3);
    const int w = tid & 3;
    const int hj = (g << 2) + w;
    float cst[2] = {0.f, 0.f};

    uint32_t cp_dst[8];
    int      cp_src[8];
    {
        uint32_t sh_h_base = (uint32_t)__cvta_generic_to_shared(sh_h);
#pragma unroll
        for (int i = 0; i < 8; ++i) {
            int s = i * 256 + tid;
            int kk = s >> 5;
            int b4 = (s & 31) << 2;
            cp_dst[i] = sh_h_base + (uint32_t)(kk * HP + b4) * 4u;
            cp_src[i] = kk * NB + b4;
        }
    }
    const uint32_t buf_bytes = (uint32_t)(KC * HP) * 4u;

    __syncthreads();

    for (int t = 0; t < NT; ++t) {
        // ---- coalesced zx prefetch (hidden behind GEMM) ----
        const float* zxc = g_zx + ((size_t)t * NG + gcol) * NB + rb;
        const float4 z0 = __ldg((const float4*)zxc);
        const float4 z1 = __ldg((const float4*)(zxc + 4));

        unsigned long long acc2[4] = {0ull, 0ull, 0ull, 0ull};  // 8 rows packed

        if (t > 0) {
            const float* hbuf = g_hbuf[(t + 1) & 1];   // written at t-1
            const unsigned tgt = 16u * (unsigned)t;

            // prologue: own group first (ready soonest), into buffer 0
            wait_ge(&g_arrive[grp], tgt);
#pragma unroll
            for (int i = 0; i < 8; ++i)
                cpa16(cp_dst[i], hbuf + grp * (KC * NB) + cp_src[i]);
            cpa_commit();

            for (int i = 0; i < NCHUNK; ++i) {
                int cur = grp + i; if (cur >= NCHUNK) cur -= NCHUNK;
                cpa_wait0();             // chunk cur resident
                __syncthreads();         // + all warps done reading other buffer
                if (i < NCHUNK - 1) {
                    int nx = cur + 1; if (nx >= NCHUNK) nx -= NCHUNK;
                    wait_ge(&g_arrive[nx], tgt);
                    const float* src = hbuf + nx * (KC * NB);
                    uint32_t dofs = ((i + 1) & 1) ? buf_bytes : 0u;
#pragma unroll
                    for (int j = 0; j < 8; ++j)
                        cpa16(cp_dst[j] + dofs, src + cp_src[j]);
                    cpa_commit();
                }
                const float* hb = sh_h + ((i & 1) ? KC * HP : 0);
                const double* whk = (const double*)sh_wh2 + cur * KC * 16;
#pragma unroll 8
                for (int kk = 0; kk < KC; ++kk) {
                    const unsigned long long w2 =
                        *(const unsigned long long*)&whk[kk * 16 + col];
                    const ulonglong2 h01 = *(const ulonglong2*)&hb[kk * HP + rb];
                    const ulonglong2 h23 = *(const ulonglong2*)&hb[kk * HP + rb + 4];
                    FMA2(acc2[0], h01.x, w2);
                    FMA2(acc2[1], h01.y, w2);
                    FMA2(acc2[2], h23.x, w2);
                    FMA2(acc2[3], h23.y, w2);
                }
            }
            __syncthreads();             // all global h reads of step t complete
            if (tid == 0) red_add(&g_gemm_done, 1u);
        }

        // z = h@Wh + zx  -> smem (unpack packed accumulators)
        {
            float a[8];
#pragma unroll
            for (int p = 0; p < 4; ++p) {
                a[2 * p]     = __uint_as_float((unsigned)(acc2[p] & 0xFFFFFFFFull));
                a[2 * p + 1] = __uint_as_float((unsigned)(acc2[p] >> 32));
            }
            sh_z[(rb + 0) * 16 + col] = a[0] + z0.x;
            sh_z[(rb + 1) * 16 + col] = a[1] + z0.y;
            sh_z[(rb + 2) * 16 + col] = a[2] + z0.z;
            sh_z[(rb + 3) * 16 + col] = a[3] + z0.w;
            sh_z[(rb + 4) * 16 + col] = a[4] + z1.x;
            sh_z[(rb + 5) * 16 + col] = a[5] + z1.y;
            sh_z[(rb + 6) * 16 + col] = a[6] + z1.z;
            sh_z[(rb + 7) * 16 + col] = a[7] + z1.w;
        }
        __syncthreads();

        // WAR guard: writing hbuf[t&1] requires all step t-1 GEMM reads done
        if (t >= 2) wait_ge(&g_gemm_done, 128u * (unsigned)(t - 1));

        // gates: 2 cells per thread
        float* hout = g_hbuf[t & 1];
#pragma unroll
        for (int u = 0; u < 2; ++u) {
            int b = (tid + u * 256) >> 2;
            float zi = sh_z[b * 16 + 0 + w];
            float zf = sh_z[b * 16 + 4 + w];
            float zg = sh_z[b * 16 + 8 + w];
            float zo = sh_z[b * 16 + 12 + w];
            float si = fsigmoid(zi);
            float sf = fsigmoid(zf);
            float tg = ftanh(zg);
            float so = fsigmoid(zo);
            float cn = sf * cst[u] + si * tg;
            cst[u] = cn;
            float hn = so * ftanh(cn);
            __stcg(&hout[hj * NB + b], hn);                       // transposed h
            out[(size_t)b * NT * NH + (size_t)t * NH + hj] = hn;  // outputs[b][t][hj]
            if (t == NT - 1) {
                out[(size_t)NB * NT * NH + (size_t)b * NH + hj] = hn;              // hT
                out[(size_t)NB * NT * NH + (size_t)NB * NH + (size_t)b * NH + hj] = cn; // cT
            }
        }

        // publish this CTA's h columns for step t
        __threadfence();
        __syncthreads();
        if (tid == 0) red_add(&g_arrive[grp], 1u);
    }
}

// -------------------- launch --------------------
extern "C" void kernel_launch(void* const* d_in, const int* in_sizes, int n_in,
                              void* d_out, int out_size) {
    const float* x    = (const float*)d_in[0];  // [B,T,D]
    const float* Wx   = (const float*)d_in[1];  // [D,4H]
    const float* Wh   = (const float*)d_in[2];  // [H,4H]
    const float* bias = (const float*)d_in[3];  // [4H]
    float* out = (float*)d_out;

    sync_init<<<1, 32>>>();

    dim3 g1(NG / 64, (NT * NB) / 128);          // (32, 512)
    zx_gemm<<<g1, 256>>>(x, Wx, bias);

    const int smem_bytes = (NH * 16 * 2 + 2 * KC * HP + NB * 16) * (int)sizeof(float); // 141312
    cudaFuncSetAttribute(lstm_persistent,
                         cudaFuncAttributeMaxDynamicSharedMemorySize, smem_bytes);
    lstm_persistent<<<NCTA, 256, smem_bytes>>>(Wh, out);
}

// round 11
// speedup vs baseline: 1.0332x; 1.0332x over previous
#include <cuda_runtime.h>
#include <stdint.h>
#include <math.h>

#define NB 128      // batch
#define NT 512      // time steps
#define ND 256      // input dim
#define NH 512      // hidden dim
#define NG 2048     // 4*NH
#define NCTA 128    // persistent grid size (all resident)
#define KC 64       // K-chunk for recurrent GEMM
#define HP 132      // smem pitch (floats) for transposed h chunk; 528B = 33*16B
#define NCHUNK (NH / KC)   // 8
#define NGROUP 8           // CTA groups of 16; group G produces h cols [G*64,(G+1)*64)
#define REP 32             // flag replica stride (uints) = 128B

// packed fp32x2 FMA
#define FMA2(d, a, b) \
    asm("fma.rn.f32x2 %0, %1, %2, %0;" : "+l"(d) : "l"(a), "l"(b))
#define PACK2(out, v) \
    asm("mov.b64 %0, {%1, %1};" : "=l"(out) : "r"(__float_as_uint(v)))

// -------------------- device scratch (no allocs allowed) --------------------
// zx stored TRANSPOSED: g_zx[t][col][b]  (col = gate*512 + hj)
__device__ float g_zx[(size_t)NT * NG * NB];
__device__ float g_hbuf[2][NH * NB];           // transposed hidden state: [hj][b]
// replicated arrival flags: group G, replica R at [G*8*REP + R*REP]
__device__ unsigned g_arrive[NGROUP * 8 * REP];

// -------------------- cp.async helpers --------------------
__device__ __forceinline__ void cpa16(uint32_t dst_smem, const void* src) {
    asm volatile("cp.async.cg.shared.global [%0], [%1], 16;\n"
                 :: "r"(dst_smem), "l"(src));
}
__device__ __forceinline__ void cpa_commit() {
    asm volatile("cp.async.commit_group;\n");
}
__device__ __forceinline__ void cpa_wait0() {
    asm volatile("cp.async.wait_group 0;\n");
}

// -------------------- flag ops --------------------
__device__ __forceinline__ void wait_ge(const unsigned* p, unsigned target) {
    unsigned v;
    asm volatile("ld.acquire.gpu.global.u32 %0, [%1];" : "=r"(v) : "l"(p));
    while (v < target) {
        __nanosleep(64);
        asm volatile("ld.acquire.gpu.global.u32 %0, [%1];" : "=r"(v) : "l"(p));
    }
}
__device__ __forceinline__ void red_release(unsigned* p, unsigned v) {
    asm volatile("red.release.gpu.global.add.u32 [%0], %1;" :: "l"(p), "r"(v));
}

// -------------------- fast activations (budget: rel_err < 1e-3) ------------
__device__ __forceinline__ float fsigmoid(float x) {
    return 1.f / (1.f + __expf(-x));
}
__device__ __forceinline__ float ftanh(float x) {
    return 1.f - 2.f / (1.f + __expf(2.f * x));
}

// -------------------- init kernel: reset counters each replay ---------------
__global__ void sync_init() {
    for (int i = threadIdx.x; i < NGROUP * 8 * REP; i += blockDim.x)
        g_arrive[i] = 0u;
}

// -------------------- Phase 1: zx_t[t][col][b] = (x@Wx + b) transposed ------
__global__ void __launch_bounds__(256) zx_gemm(const float* __restrict__ x,
                                               const float* __restrict__ Wx,
                                               const float* __restrict__ bias) {
    __shared__ float shAT[16 * HP];   // [kk][b] transposed A tile
    __shared__ float shB[16 * 64];    // [kk][j]

    const int nt = blockIdx.x;        // 0..31
    const int mt = blockIdx.y;        // 0..511  (== t, tile M = 128 = NB)
    const int tid = threadIdx.x;
    const int c0 = (tid & 15) << 2;
    const int r0 = (tid >> 4) << 3;

    unsigned long long acc2[4][4];    // [row-pair][col], packed fp32x2
#pragma unroll
    for (int p = 0; p < 4; ++p)
#pragma unroll
        for (int c = 0; c < 4; ++c) acc2[p][c] = 0ull;

    for (int k0 = 0; k0 < ND; k0 += 16) {
#pragma unroll
        for (int i = 0; i < 8; ++i) {
            int flat = i * 256 + tid;
            int kk = flat & 15;
            int b = flat >> 4;
            shAT[kk * HP + b] = x[(size_t)b * (NT * ND) + (size_t)mt * ND + k0 + kk];
        }
#pragma unroll
        for (int i = 0; i < 4; ++i) {
            int flat = i * 256 + tid;
            int j = flat & 63;
            int kk = flat >> 6;
            shB[kk * 64 + j] = Wx[(size_t)(k0 + kk) * NG + nt * 64 + j];
        }
        __syncthreads();
#pragma unroll
        for (int kk = 0; kk < 16; ++kk) {
            const float4 b4 = *(const float4*)&shB[kk * 64 + c0];
            unsigned long long bd[4];
            PACK2(bd[0], b4.x); PACK2(bd[1], b4.y);
            PACK2(bd[2], b4.z); PACK2(bd[3], b4.w);
            const ulonglong2 a01 = *(const ulonglong2*)&shAT[kk * HP + r0];
            const ulonglong2 a23 = *(const ulonglong2*)&shAT[kk * HP + r0 + 4];
            const unsigned long long ap[4] = {a01.x, a01.y, a23.x, a23.y};
#pragma unroll
            for (int p = 0; p < 4; ++p)
#pragma unroll
                for (int c = 0; c < 4; ++c) FMA2(acc2[p][c], ap[p], bd[c]);
        }
        __syncthreads();
    }

#pragma unroll
    for (int c = 0; c < 4; ++c) {
        const float bc = bias[nt * 64 + c0 + c];
        float a[8];
#pragma unroll
        for (int p = 0; p < 4; ++p) {
            a[2 * p]     = __uint_as_float((unsigned)(acc2[p][c] & 0xFFFFFFFFull)) + bc;
            a[2 * p + 1] = __uint_as_float((unsigned)(acc2[p][c] >> 32)) + bc;
        }
        size_t base = ((size_t)mt * NG + nt * 64 + c0 + c) * NB + r0;
        *(float4*)&g_zx[base]     = make_float4(a[0], a[1], a[2], a[3]);
        *(float4*)&g_zx[base + 4] = make_float4(a[4], a[5], a[6], a[7]);
    }
}

// -------------------- Phase 2: persistent recurrent kernel ------------------
// CTA g owns h-columns [4g, 4g+4) and z-columns {gate*512 + 4g + w}.
// Flag sync: tid0-only polling of replicated per-group counters; WAR guard
// is implied by the 8 chunk flag-waits (publish happens after reads).
__global__ void __launch_bounds__(256, 1) lstm_persistent(
    const float* __restrict__ Wh, float* __restrict__ out) {
    extern __shared__ float smem[];
    float* sh_wh2 = smem;                              // [512][16] float2
    float* sh_h   = smem + NH * 16 * 2;                // [2][KC][HP]
    float* sh_z   = smem + NH * 16 * 2 + 2 * KC * HP;  // [128][16]

    const int g = blockIdx.x;    // 0..127
    const int tid = threadIdx.x;
    const int grp = g >> 4;      // own producer group (= consumer replica id)

    // Wh slice, duplicated into both lanes of a float2
    for (int i = tid; i < NH * 16; i += 256) {
        int k = i >> 4, c = i & 15;
        int gcol = ((c >> 2) << 9) + (g << 2) + (c & 3);  // gate*512 + 4g + w
        float wv = Wh[(size_t)k * NG + gcol];
        ((float2*)sh_wh2)[i] = make_float2(wv, wv);
    }

    const int col = tid & 15;
    const int rb = (tid >> 4) << 3;
    const int gcol = ((col >> 2) << 9) + (g << 2) + (col & 3);
    const int w = tid & 3;
    const int hj = (g << 2) + w;
    float cst[2] = {0.f, 0.f};

    uint32_t cp_dst[8];
    int      cp_src[8];
    {
        uint32_t sh_h_base = (uint32_t)__cvta_generic_to_shared(sh_h);
#pragma unroll
        for (int i = 0; i < 8; ++i) {
            int s = i * 256 + tid;
            int kk = s >> 5;
            int b4 = (s & 31) << 2;
            cp_dst[i] = sh_h_base + (uint32_t)(kk * HP + b4) * 4u;
            cp_src[i] = kk * NB + b4;
        }
    }
    const uint32_t buf_bytes = (uint32_t)(KC * HP) * 4u;

    __syncthreads();

    for (int t = 0; t < NT; ++t) {
        // ---- coalesced zx prefetch (hidden behind GEMM) ----
        const float* zxc = g_zx + ((size_t)t * NG + gcol) * NB + rb;
        const float4 z0 = __ldg((const float4*)zxc);
        const float4 z1 = __ldg((const float4*)(zxc + 4));

        unsigned long long acc2[4] = {0ull, 0ull, 0ull, 0ull};  // 8 rows packed

        if (t > 0) {
            const float* hbuf = g_hbuf[(t + 1) & 1];   // written at t-1
            const unsigned tgt = 16u * (unsigned)t;

            // prologue: own group first; tid0 polls replica grp, barrier spreads
            if (tid == 0) wait_ge(&g_arrive[(grp * 8 + grp) * REP], tgt);
            __syncthreads();
#pragma unroll
            for (int i = 0; i < 8; ++i)
                cpa16(cp_dst[i], hbuf + grp * (KC * NB) + cp_src[i]);
            cpa_commit();

            for (int i = 0; i < NCHUNK; ++i) {
                int cur = grp + i; if (cur >= NCHUNK) cur -= NCHUNK;
                int nx = cur + 1; if (nx >= NCHUNK) nx -= NCHUNK;
                cpa_wait0();             // chunk cur resident (this thread)
                if (i < NCHUNK - 1 && tid == 0)
                    wait_ge(&g_arrive[(nx * 8 + grp) * REP], tgt);
                __syncthreads();         // chunk ready + flag ok + prev compute done
                if (i < NCHUNK - 1) {
                    const float* src = hbuf + nx * (KC * NB);
                    uint32_t dofs = ((i + 1) & 1) ? buf_bytes : 0u;
#pragma unroll
                    for (int j = 0; j < 8; ++j)
                        cpa16(cp_dst[j] + dofs, src + cp_src[j]);
                    cpa_commit();
                }
                const float* hb = sh_h + ((i & 1) ? KC * HP : 0);
                const double* whk = (const double*)sh_wh2 + cur * KC * 16;
#pragma unroll 8
                for (int kk = 0; kk < KC; ++kk) {
                    const unsigned long long w2 =
                        *(const unsigned long long*)&whk[kk * 16 + col];
                    const ulonglong2 h01 = *(const ulonglong2*)&hb[kk * HP + rb];
                    const ulonglong2 h23 = *(const ulonglong2*)&hb[kk * HP + rb + 4];
                    FMA2(acc2[0], h01.x, w2);
                    FMA2(acc2[1], h01.y, w2);
                    FMA2(acc2[2], h23.x, w2);
                    FMA2(acc2[3], h23.y, w2);
                }
            }
        }

        // z = h@Wh + zx  -> smem (unpack packed accumulators)
        {
            float a[8];
#pragma unroll
            for (int p = 0; p < 4; ++p) {
                a[2 * p]     = __uint_as_float((unsigned)(acc2[p] & 0xFFFFFFFFull));
                a[2 * p + 1] = __uint_as_float((unsigned)(acc2[p] >> 32));
            }
            sh_z[(rb + 0) * 16 + col] = a[0] + z0.x;
            sh_z[(rb + 1) * 16 + col] = a[1] + z0.y;
            sh_z[(rb + 2) * 16 + col] = a[2] + z0.z;
            sh_z[(rb + 3) * 16 + col] = a[3] + z0.w;
            sh_z[(rb + 4) * 16 + col] = a[4] + z1.x;
            sh_z[(rb + 5) * 16 + col] = a[5] + z1.y;
            sh_z[(rb + 6) * 16 + col] = a[6] + z1.z;
            sh_z[(rb + 7) * 16 + col] = a[7] + z1.w;
        }
        __syncthreads();

        // gates: 2 cells per thread
        float* hout = g_hbuf[t & 1];
#pragma unroll
        for (int u = 0; u < 2; ++u) {
            int b = (tid + u * 256) >> 2;
            float zi = sh_z[b * 16 + 0 + w];
            float zf = sh_z[b * 16 + 4 + w];
            float zg = sh_z[b * 16 + 8 + w];
            float zo = sh_z[b * 16 + 12 + w];
            float si = fsigmoid(zi);
            float sf = fsigmoid(zf);
            float tg = ftanh(zg);
            float so = fsigmoid(zo);
            float cn = sf * cst[u] + si * tg;
            cst[u] = cn;
            float hn = so * ftanh(cn);
            __stcg(&hout[hj * NB + b], hn);                       // transposed h
            out[(size_t)b * NT * NH + (size_t)t * NH + hj] = hn;  // outputs[b][t][hj]
            if (t == NT - 1) {
                out[(size_t)NB * NT * NH + (size_t)b * NH + hj] = hn;              // hT
                out[(size_t)NB * NT * NH + (size_t)NB * NH + (size_t)b * NH + hj] = cn; // cT
            }
        }

        // publish: syncthreads (CTA h-stores ordered) + cumulative release adds
        __syncthreads();
        if (tid < 8) red_release(&g_arrive[(grp * 8 + tid) * REP], 1u);
    }
}

// -------------------- launch --------------------
extern "C" void kernel_launch(void* const* d_in, const int* in_sizes, int n_in,
                              void* d_out, int out_size) {
    const float* x    = (const float*)d_in[0];  // [B,T,D]
    const float* Wx   = (const float*)d_in[1];  // [D,4H]
    const float* Wh   = (const float*)d_in[2];  // [H,4H]
    const float* bias = (const float*)d_in[3];  // [4H]
    float* out = (float*)d_out;

    sync_init<<<1, 256>>>();

    dim3 g1(NG / 64, (NT * NB) / 128);          // (32, 512)
    zx_gemm<<<g1, 256>>>(x, Wx, bias);

    const int smem_bytes = (NH * 16 * 2 + 2 * KC * HP + NB * 16) * (int)sizeof(float); // 141312
    cudaFuncSetAttribute(lstm_persistent,
                         cudaFuncAttributeMaxDynamicSharedMemorySize, smem_bytes);
    lstm_persistent<<<NCTA, 256, smem_bytes>>>(Wh, out);
}